// round 1
// baseline (speedup 1.0000x reference)
#include <cuda_runtime.h>

// ---------------------------------------------------------------------------
// Problem constants (from reference): N_MAT=8, N_MATP=8 -> materials block = 64
// N_PROCP=5, RGAS=8.314. n_data/seg derived at runtime from in_sizes.
// ---------------------------------------------------------------------------

#define TILE   8192
#define THREADS 512
#define ELEMS   16            // TILE / THREADS
#define NW      (THREADS/32)  // 16 warps

struct RowP {
    float C1;       // SigmaC - Mfda*P
    float Kb;       // BetaD * D
    float S0Kb;     // Sigma0 * Kb
    float G200;
    float alpha1;
    float L0;
    float A0;
    float invBl;    // 1/(B0*l0 + 1e-9)
    float R;
    float tscale;   // x_max - x_min
    float xmin;
    float out_base; // (K0 - y_min) * inv_y
    float inv_y;    // 1/(y_max - y_min)
    float pad0, pad1, pad2;
};

__device__ RowP g_rowp[1024];

// ---------------------------------------------------------------------------
// Parameter prep: sigmoid-squash raw params, gather material row, fold
// all row-constant algebra once.
// ---------------------------------------------------------------------------
__global__ void prep_kernel(const float* __restrict__ pc,
                            const float* __restrict__ raw,
                            const float* __restrict__ lb,
                            const float* __restrict__ ub,
                            const float* __restrict__ sc,
                            const int*   __restrict__ mi,
                            int n_data)
{
    int r = blockIdx.x * blockDim.x + threadIdx.x;
    if (r >= n_data) return;

    auto xv = [&](int i) -> float {
        float v = raw[i];
        float s = 1.0f / (1.0f + expf(-v));
        return s * (ub[i] - lb[i]) + lb[i];
    };

    const int MATB = 64;           // N_MAT * N_MATP
    int pb = MATB + r * 5;
    float SigmaC = xv(pb + 0);
    float K0     = xv(pb + 1);
    float alpha1 = xv(pb + 2);
    float L0     = xv(pb + 3);
    float G200   = xv(pb + 4);

    int mb = mi[r] * 8;
    float Sigma0 = xv(mb + 0);
    float BetaD  = xv(mb + 1);
    float Ea     = xv(mb + 2);
    float Mfda   = xv(mb + 3);
    float Di     = xv(mb + 4);
    float A0     = xv(mb + 5);
    float B0     = xv(mb + 6);
    float l0     = xv(mb + 7);

    float R = pc[4 * r + 0];
    float T = pc[4 * r + 1];
    float P = pc[4 * r + 2];

    float D  = Di * expf(-Ea / (8.314f * T));
    float Kb = BetaD * D;

    float xmin = sc[0], xmax = sc[1], ymin = sc[2], ymax = sc[3];

    RowP p;
    p.C1     = SigmaC - Mfda * P;
    p.Kb     = Kb;
    p.S0Kb   = Sigma0 * Kb;
    p.G200   = G200;
    p.alpha1 = alpha1;
    p.L0     = L0;
    p.A0     = A0;
    p.invBl  = 1.0f / (B0 * l0 + 1e-9f);
    p.R      = R;
    p.tscale = xmax - xmin;
    p.xmin   = xmin;
    p.inv_y  = 1.0f / (ymax - ymin);
    p.out_base = (K0 - ymin) * p.inv_y;
    p.pad0 = p.pad1 = p.pad2 = 0.f;

    g_rowp[r] = p;
}

// ---------------------------------------------------------------------------
// Stress at previous time point. Divides folded into ONE:
//   beta = Kb/den1,  den1 = R*Lg + 1e-9
//   sigma = (C1 + (S0/Lg)*beta) / (1+beta)
//         = (C1*Lg*den1 + S0*Kb) / (Lg*(den1 + Kb))
// 4 MUFU ops: LG2, EX2 (pow), RCP (divide), EX2 (decay exp).
// ---------------------------------------------------------------------------
__device__ __forceinline__ float stress_s(const RowP& p, float tp)
{
    float u    = fmaf(tp, 0.005f, 0.001f);       // tp/200 + 0.001
    float lnu  = __logf(u);
    float powv = __expf(p.alpha1 * lnu);         // u^alpha1
    float Lg   = fmaf(p.G200, powv, p.L0);
    float den1 = fmaf(p.R, Lg, 1e-9f);
    float num  = fmaf(p.C1 * Lg, den1, p.S0Kb);
    float den  = Lg * (den1 + p.Kb);
    float sig  = __fdividef(num, den);
    return fmaf(p.A0, __expf(-tp * p.invBl), sig);
}

// ---------------------------------------------------------------------------
// One persistent block per row. Sequential tiles of 8192, register carry.
// Blocked float4 loads + register prefetch of next tile; shuffle block scan.
// ---------------------------------------------------------------------------
__global__ void __launch_bounds__(THREADS)
scan_kernel(const float* __restrict__ x, float* __restrict__ out, int seg)
{
    __shared__ float s_warp[NW];

    const int row  = blockIdx.x;
    const RowP p   = g_rowp[row];
    const float* xr   = x   + (size_t)row * (size_t)seg;
    float*       outr = out + (size_t)row * (size_t)seg;

    const int tid  = threadIdx.x;
    const int lane = tid & 31;
    const int wid  = tid >> 5;

    const int fullTiles = seg / TILE;
    const int rem       = seg - fullTiles * TILE;

    float carry = 0.0f;

    float4 pf0, pf1, pf2, pf3;
    float  pfh = 0.0f;

    if (fullTiles > 0) {
        int j0 = tid * ELEMS;
        pf0 = *(const float4*)(xr + j0);
        pf1 = *(const float4*)(xr + j0 + 4);
        pf2 = *(const float4*)(xr + j0 + 8);
        pf3 = *(const float4*)(xr + j0 + 12);
        pfh = (j0 > 0) ? xr[j0 - 1] : xr[0];
    }

    for (int tile = 0; tile < fullTiles; ++tile) {
        const int j0 = tile * TILE + tid * ELEMS;

        float xv[ELEMS];
        xv[0]=pf0.x; xv[1]=pf0.y; xv[2]=pf0.z;  xv[3]=pf0.w;
        xv[4]=pf1.x; xv[5]=pf1.y; xv[6]=pf1.z;  xv[7]=pf1.w;
        xv[8]=pf2.x; xv[9]=pf2.y; xv[10]=pf2.z; xv[11]=pf2.w;
        xv[12]=pf3.x; xv[13]=pf3.y; xv[14]=pf3.z; xv[15]=pf3.w;
        float xprev = pfh;

        // prefetch next full tile (latency overlaps the MUFU-heavy compute)
        if (tile + 1 < fullTiles) {
            int n0 = j0 + TILE;
            pf0 = *(const float4*)(xr + n0);
            pf1 = *(const float4*)(xr + n0 + 4);
            pf2 = *(const float4*)(xr + n0 + 8);
            pf3 = *(const float4*)(xr + n0 + 12);
            pfh = xr[n0 - 1];
        }

        // per-thread serial (inclusive) scan of 16 contributions
        float tprev = fmaf(xprev, p.tscale, p.xmin);
        float run = 0.0f;
        float inc[ELEMS];
        #pragma unroll
        for (int k = 0; k < ELEMS; ++k) {
            float tcur = fmaf(xv[k], p.tscale, p.xmin);
            float c = stress_s(p, tprev) * (tcur - tprev);
            if (k == 0 && j0 == 0) c = 0.0f;   // out[0] = K0
            run += c;
            inc[k] = run;
            tprev = tcur;
        }

        // block scan of per-thread sums
        float v = run;
        #pragma unroll
        for (int d = 1; d < 32; d <<= 1) {
            float n = __shfl_up_sync(0xffffffffu, v, d);
            if (lane >= d) v += n;
        }
        if (lane == 31) s_warp[wid] = v;
        __syncthreads();
        if (wid == 0) {
            float w = (lane < NW) ? s_warp[lane] : 0.0f;
            #pragma unroll
            for (int d = 1; d < NW; d <<= 1) {
                float n = __shfl_up_sync(0xffffffffu, w, d);
                if (lane >= d) w += n;
            }
            if (lane < NW) s_warp[lane] = w;
        }
        __syncthreads();

        float base  = carry + (wid ? s_warp[wid - 1] : 0.0f) + (v - run);
        float total = s_warp[NW - 1];

        #pragma unroll
        for (int k = 0; k < ELEMS; k += 4) {
            float4 o;
            o.x = fmaf(base + inc[k + 0], p.inv_y, p.out_base);
            o.y = fmaf(base + inc[k + 1], p.inv_y, p.out_base);
            o.z = fmaf(base + inc[k + 2], p.inv_y, p.out_base);
            o.w = fmaf(base + inc[k + 3], p.inv_y, p.out_base);
            *(float4*)(outr + j0 + k) = o;
        }

        carry += total;
        __syncthreads();   // protect s_warp reuse next tile
    }

    // ---- guarded remainder tile (not hit for seg=131072, kept for safety) ----
    if (rem > 0) {
        const int S  = fullTiles * TILE;
        const int j0 = S + tid * ELEMS;

        float xv[ELEMS];
        #pragma unroll
        for (int k = 0; k < ELEMS; ++k)
            xv[k] = (j0 + k < seg) ? xr[j0 + k] : 0.0f;
        float xprev = (j0 > 0 && j0 <= seg) ? xr[j0 - 1] : 0.0f;

        float tprev = fmaf(xprev, p.tscale, p.xmin);
        float run = 0.0f;
        float inc[ELEMS];
        #pragma unroll
        for (int k = 0; k < ELEMS; ++k) {
            float c = 0.0f;
            if (j0 + k < seg) {
                float tcur = fmaf(xv[k], p.tscale, p.xmin);
                c = stress_s(p, tprev) * (tcur - tprev);
                if (j0 + k == 0) c = 0.0f;
                tprev = tcur;
            }
            run += c;
            inc[k] = run;
        }

        float v = run;
        #pragma unroll
        for (int d = 1; d < 32; d <<= 1) {
            float n = __shfl_up_sync(0xffffffffu, v, d);
            if (lane >= d) v += n;
        }
        if (lane == 31) s_warp[wid] = v;
        __syncthreads();
        if (wid == 0) {
            float w = (lane < NW) ? s_warp[lane] : 0.0f;
            #pragma unroll
            for (int d = 1; d < NW; d <<= 1) {
                float n = __shfl_up_sync(0xffffffffu, w, d);
                if (lane >= d) w += n;
            }
            if (lane < NW) s_warp[lane] = w;
        }
        __syncthreads();

        float base = carry + (wid ? s_warp[wid - 1] : 0.0f) + (v - run);
        #pragma unroll
        for (int k = 0; k < ELEMS; ++k) {
            if (j0 + k < seg)
                outr[j0 + k] = fmaf(base + inc[k], p.inv_y, p.out_base);
        }
    }
}

// ---------------------------------------------------------------------------
// Launch. Inputs (metadata order): x_scaled f32, process_c f32[N,4],
// raw_params f32, para_lb f32, para_ub f32, scaler_params f32[4],
// fit_index i32 (unused), material_index i32[N]. Output f32.
// ---------------------------------------------------------------------------
extern "C" void kernel_launch(void* const* d_in, const int* in_sizes, int n_in,
                              void* d_out, int out_size)
{
    const float* x   = (const float*)d_in[0];
    const float* pc  = (const float*)d_in[1];
    const float* raw = (const float*)d_in[2];
    const float* lb  = (const float*)d_in[3];
    const float* ub  = (const float*)d_in[4];
    const float* sc  = (const float*)d_in[5];
    const int*   mi  = (const int*)  d_in[7];

    int n_data = in_sizes[1] / 4;
    int seg    = in_sizes[0] / n_data;

    prep_kernel<<<(n_data + 127) / 128, 128>>>(pc, raw, lb, ub, sc, mi, n_data);
    scan_kernel<<<n_data, THREADS>>>(x, (float*)d_out, seg);
}

// round 3
// speedup vs baseline: 1.1911x; 1.1911x over previous
#include <cuda_runtime.h>

// ---------------------------------------------------------------------------
// Decoupled-lookback stream scan over 128 independent rows.
// Each block owns one 4096-element chunk of one row: computes s*dT once
// (registers), publishes aggregate, warp-parallel lookback for prefix,
// writes output. State word = (flag<<32)|float : single 64-bit atom, so
// no separate fence is needed between payload and flag.
// ---------------------------------------------------------------------------

#define THREADS 256
#define ELEMS   16
#define CHUNK   (THREADS * ELEMS)   // 4096
#define NW      (THREADS / 32)      // 8 warps

struct RowP {
    float C1;       // SigmaC - Mfda*P
    float Kb;       // BetaD * D
    float S0Kb;     // Sigma0 * Kb
    float G200;
    float alpha1;
    float L0;
    float A0;
    float invBl2;   // log2(e) / (B0*l0 + 1e-9)
    float R;
    float tscale;   // x_max - x_min
    float xmin;
    float out_base; // (K0 - y_min) * inv_y
    float inv_y;    // 1/(y_max - y_min)
    float pad0, pad1, pad2;
};

__device__ RowP g_rowp[1024];
// flag: 0 = invalid, 1 = aggregate ready, 2 = inclusive prefix ready.
__device__ unsigned long long g_state[32768];

// ---------------------------------------------------------------------------
__global__ void reset_kernel(int n)
{
    int i = blockIdx.x * blockDim.x + threadIdx.x;
    if (i < n) g_state[i] = 0ULL;
}

// ---------------------------------------------------------------------------
__global__ void prep_kernel(const float* __restrict__ pc,
                            const float* __restrict__ raw,
                            const float* __restrict__ lb,
                            const float* __restrict__ ub,
                            const float* __restrict__ sc,
                            const int*   __restrict__ mi,
                            int n_data)
{
    int r = blockIdx.x * blockDim.x + threadIdx.x;
    if (r >= n_data) return;

    auto xv = [&](int i) -> float {
        float v = raw[i];
        float s = 1.0f / (1.0f + expf(-v));
        return s * (ub[i] - lb[i]) + lb[i];
    };

    const int MATB = 64;           // N_MAT * N_MATP
    int pb = MATB + r * 5;
    float SigmaC = xv(pb + 0);
    float K0     = xv(pb + 1);
    float alpha1 = xv(pb + 2);
    float L0     = xv(pb + 3);
    float G200   = xv(pb + 4);

    int mb = mi[r] * 8;
    float Sigma0 = xv(mb + 0);
    float BetaD  = xv(mb + 1);
    float Ea     = xv(mb + 2);
    float Mfda   = xv(mb + 3);
    float Di     = xv(mb + 4);
    float A0     = xv(mb + 5);
    float B0     = xv(mb + 6);
    float l0     = xv(mb + 7);

    float R = pc[4 * r + 0];
    float T = pc[4 * r + 1];
    float P = pc[4 * r + 2];

    float D  = Di * expf(-Ea / (8.314f * T));
    float Kb = BetaD * D;

    float xmin = sc[0], xmax = sc[1], ymin = sc[2], ymax = sc[3];

    RowP p;
    p.C1     = SigmaC - Mfda * P;
    p.Kb     = Kb;
    p.S0Kb   = Sigma0 * Kb;
    p.G200   = G200;
    p.alpha1 = alpha1;
    p.L0     = L0;
    p.A0     = A0;
    p.invBl2 = 1.44269504f / (B0 * l0 + 1e-9f);
    p.R      = R;
    p.tscale = xmax - xmin;
    p.xmin   = xmin;
    p.inv_y  = 1.0f / (ymax - ymin);
    p.out_base = (K0 - ymin) * p.inv_y;
    p.pad0 = p.pad1 = p.pad2 = 0.f;

    g_rowp[r] = p;
}

// ---------------------------------------------------------------------------
__device__ __forceinline__ float ex2f(float x)
{ float y; asm("ex2.approx.ftz.f32 %0, %1;" : "=f"(y) : "f"(x)); return y; }
__device__ __forceinline__ float lg2f(float x)
{ float y; asm("lg2.approx.ftz.f32 %0, %1;" : "=f"(y) : "f"(x)); return y; }

// 4 MUFU ops per element: LG2, EX2 (pow), RCP (single folded divide), EX2.
//   beta = Kb/den1,  den1 = R*Lg + 1e-9
//   sigma = (C1 + (S0/Lg)*beta) / (1+beta)
//         = (C1*Lg*den1 + S0*Kb) / (Lg*(den1 + Kb))
__device__ __forceinline__ float stress_s(const RowP& p, float tp)
{
    float u    = fmaf(tp, 0.005f, 0.001f);           // tp/200 + 0.001
    float powv = ex2f(p.alpha1 * lg2f(u));           // u^alpha1
    float Lg   = fmaf(p.G200, powv, p.L0);
    float den1 = fmaf(p.R, Lg, 1e-9f);
    float num  = fmaf(p.C1 * Lg, den1, p.S0Kb);
    float den  = Lg * (den1 + p.Kb);
    float sig  = __fdividef(num, den);
    return fmaf(p.A0, ex2f(-tp * p.invBl2), sig);
}

__device__ __forceinline__ unsigned long long pack_state(unsigned flag, float v)
{
    return ((unsigned long long)flag << 32) | (unsigned long long)__float_as_uint(v);
}

// ---------------------------------------------------------------------------
__global__ void __launch_bounds__(THREADS)
scan_kernel(const float* __restrict__ x, float* __restrict__ out,
            int seg, int cpr)
{
    __shared__ float s_warp[NW];
    __shared__ float s_prefix;

    const int bid = blockIdx.x;
    const int row = bid / cpr;
    const int cix = bid - row * cpr;
    const RowP p  = g_rowp[row];
    const float* xr   = x   + (size_t)row * (size_t)seg;
    float*       outr = out + (size_t)row * (size_t)seg;

    const int tid  = threadIdx.x;
    const int lane = tid & 31;
    const int wid  = tid >> 5;
    const int j0   = cix * CHUNK + tid * ELEMS;

    // ---- load 17 inputs (16 + left neighbor) --------------------------------
    float xv[ELEMS];
    const bool full = (j0 + ELEMS <= seg);
    if (full) {
        float4 a  = *(const float4*)(xr + j0);
        float4 b  = *(const float4*)(xr + j0 + 4);
        float4 c4 = *(const float4*)(xr + j0 + 8);
        float4 d  = *(const float4*)(xr + j0 + 12);
        xv[0]=a.x;  xv[1]=a.y;  xv[2]=a.z;  xv[3]=a.w;
        xv[4]=b.x;  xv[5]=b.y;  xv[6]=b.z;  xv[7]=b.w;
        xv[8]=c4.x; xv[9]=c4.y; xv[10]=c4.z;xv[11]=c4.w;
        xv[12]=d.x; xv[13]=d.y; xv[14]=d.z; xv[15]=d.w;
    } else {
        #pragma unroll
        for (int k = 0; k < ELEMS; ++k)
            xv[k] = (j0 + k < seg) ? xr[j0 + k] : 0.0f;
    }
    float xprev = (j0 > 0 && j0 <= seg) ? xr[j0 - 1] : 0.0f;

    // ---- per-thread serial inclusive scan of 16 contributions ---------------
    float tprev = fmaf(xprev, p.tscale, p.xmin);
    float run   = 0.0f;
    float inc[ELEMS];
    #pragma unroll
    for (int k = 0; k < ELEMS; ++k) {
        float c = 0.0f;
        if (full || (j0 + k < seg)) {
            float tcur = fmaf(xv[k], p.tscale, p.xmin);
            c = stress_s(p, tprev) * (tcur - tprev);
            if (j0 + k == 0) c = 0.0f;       // out[0] = K0
            tprev = tcur;
        }
        run += c;
        inc[k] = run;
    }

    // ---- block scan of per-thread sums --------------------------------------
    float v = run;
    #pragma unroll
    for (int d = 1; d < 32; d <<= 1) {
        float n = __shfl_up_sync(0xffffffffu, v, d);
        if (lane >= d) v += n;
    }
    if (lane == 31) s_warp[wid] = v;
    __syncthreads();
    if (wid == 0) {
        float w = (lane < NW) ? s_warp[lane] : 0.0f;
        #pragma unroll
        for (int d = 1; d < NW; d <<= 1) {
            float n = __shfl_up_sync(0xffffffffu, w, d);
            if (lane >= d) w += n;
        }
        if (lane < NW) s_warp[lane] = w;
    }
    __syncthreads();

    const float total = s_warp[NW - 1];
    const float exc   = (wid ? s_warp[wid - 1] : 0.0f) + (v - run);

    // ---- publish + warp-parallel decoupled lookback (warp 0) ----------------
    if (wid == 0) {
        float running = 0.0f;
        if (cix != 0) {
            if (lane == 0)
                atomicExch(&g_state[bid], pack_state(1u, total));

            const int rowStart = bid - cix;   // first chunk of this row
            int base = bid - 1;               // lane 0 = nearest predecessor
            for (;;) {
                int idx = base - lane;
                unsigned long long s;
                if (idx >= rowStart) {
                    s = ((volatile unsigned long long*)g_state)[idx];
                } else {
                    s = pack_state(2u, 0.0f);         // virtual prefix 0
                }
                unsigned f   = (unsigned)(s >> 32);
                unsigned rdy = __ballot_sync(0xffffffffu, f != 0u);
                unsigned pre = __ballot_sync(0xffffffffu, f == 2u);
                // mask of lanes we need: up to & including first prefix lane,
                // or all 32 if no prefix in window (cpr>32 generalization).
                unsigned need = pre ? (unsigned)((1ull << __ffs(pre)) - 1ull)
                                    : 0xffffffffu;
                if ((rdy & need) == need) {
                    int firstP = pre ? (__ffs(pre) - 1) : 32;
                    float val = (lane <= firstP || !pre)
                              ? __uint_as_float((unsigned)(s & 0xffffffffu))
                              : 0.0f;
                    #pragma unroll
                    for (int d = 16; d; d >>= 1)
                        val += __shfl_xor_sync(0xffffffffu, val, d);
                    running += val;
                    if (pre) break;
                    base -= 32;
                } else {
                    __nanosleep(40);
                }
            }
        }
        if (lane == 0) {
            atomicExch(&g_state[bid], pack_state(2u, running + total));
            s_prefix = running;
        }
    }
    __syncthreads();

    // ---- output: fit = K0 + prefix; scale to (y - ymin)/(ymax - ymin) -------
    const float bb = fmaf(s_prefix + exc, p.inv_y, p.out_base);

    if (full) {
        #pragma unroll
        for (int k = 0; k < ELEMS; k += 4) {
            float4 o;
            o.x = fmaf(inc[k + 0], p.inv_y, bb);
            o.y = fmaf(inc[k + 1], p.inv_y, bb);
            o.z = fmaf(inc[k + 2], p.inv_y, bb);
            o.w = fmaf(inc[k + 3], p.inv_y, bb);
            *(float4*)(outr + j0 + k) = o;
        }
    } else {
        #pragma unroll
        for (int k = 0; k < ELEMS; ++k)
            if (j0 + k < seg)
                outr[j0 + k] = fmaf(inc[k], p.inv_y, bb);
    }
}

// ---------------------------------------------------------------------------
// Inputs (metadata order): x_scaled f32, process_c f32[N,4], raw_params f32,
// para_lb f32, para_ub f32, scaler_params f32[4], fit_index i32 (unused),
// material_index i32[N]. Output f32.
// ---------------------------------------------------------------------------
extern "C" void kernel_launch(void* const* d_in, const int* in_sizes, int n_in,
                              void* d_out, int out_size)
{
    const float* x   = (const float*)d_in[0];
    const float* pc  = (const float*)d_in[1];
    const float* raw = (const float*)d_in[2];
    const float* lb  = (const float*)d_in[3];
    const float* ub  = (const float*)d_in[4];
    const float* sc  = (const float*)d_in[5];
    const int*   mi  = (const int*)  d_in[7];

    int n_data  = in_sizes[1] / 4;
    int seg     = in_sizes[0] / n_data;
    int cpr     = (seg + CHUNK - 1) / CHUNK;
    int nchunks = n_data * cpr;

    reset_kernel<<<(nchunks + 255) / 256, 256>>>(nchunks);
    prep_kernel<<<(n_data + 127) / 128, 128>>>(pc, raw, lb, ub, sc, mi, n_data);
    scan_kernel<<<nchunks, THREADS>>>(x, (float*)d_out, seg, cpr);
}